// round 15
// baseline (speedup 1.0000x reference)
#include <cuda_runtime.h>

// Patch2Im / fold (col2im) with averaging and crop.
// Input : x_patch [B=4, C=64, K=7, K=7, NH=85, NW=85] fp32 (row-major)
// Output: [B, C, 253, 253] fp32 (padded frame 259x259, crop 3 each side)
//
// v7 = v2 (direct immediate-offset gather, best @66us) + residue-class row
// grouping for DRAM locality. Output rows oh and oh+3 share the same
// kernel-row index set and read ADJACENT plane rows (ph, ph+1) of the same
// 21 planes. A block of 5 warp-groups (96 threads each) handles 5
// same-residue rows, so each plane is read as one contiguous 5*340B = 1.7KB
// region instead of a lone 340B range -> better HBM row/bank locality, and
// misaligned boundary cache lines are recovered inside one SM's L1.
// Per-group code is identical to v2: thread t owns output cols 3t+3+e; all
// 7 loads of a kernel-row plane sit at fixed immediate offsets from
// (plane_base + t): {+1, P+1, 2P+1, 3P, 4P, 5P, 6P-1}, P = 85*85.

namespace {
constexpr int K     = 7;
constexpr int NH    = 85;
constexpr int NW    = 85;
constexpr int PLANE = NH * NW;          // 7225
constexpr int PAD   = 3;
constexpr int HO    = 253;
constexpr int WO    = 253;
constexpr int BC    = 4 * 64;
constexpr int TPG   = 96;               // threads per row-group (3 warps)
constexpr int G     = 5;                // same-residue rows per block
constexpr int TPB   = TPG * G;          // 480
constexpr int TGRP  = 85;
constexpr int CHUNKS = 17;              // ceil(85 rows-per-class / G)
}

// One kernel-row plane: 7 loads at constant immediate offsets,
// boundary groups predicated (@P LDG, no branches).
__device__ __forceinline__ void accum_plane(const float* __restrict__ q,
                                            bool p012, bool p6,
                                            float& a0, float& a1, float& a2)
{
    if (p012) {                               // pw = t+1 (t <= 83)
        a0 += __ldcs(q + 1);                  // j=0
        a1 += __ldcs(q + PLANE + 1);          // j=1
        a2 += __ldcs(q + 2 * PLANE + 1);      // j=2
    }
    a0 += __ldcs(q + 3 * PLANE);              // j=3 (pw = t)
    a1 += __ldcs(q + 4 * PLANE);              // j=4
    a2 += __ldcs(q + 5 * PLANE);              // j=5
    if (p6)                                   // pw = t-1 (t >= 1)
        a0 += __ldcs(q + 6 * PLANE - 1);      // j=6
}

__global__ __launch_bounds__(TPB, 2)
void patch2im_kernel(const float* __restrict__ xp, float* __restrict__ out)
{
    __shared__ float sm[G][TGRP * 3];

    const int tid = threadIdx.x;
    const int g   = tid / TPG;           // row-group 0..4 (warp-aligned)
    const int t   = tid - g * TPG;       // 0..95 within group
    const int bc  = blockIdx.y;

    // blockIdx.x encodes (residue class c, chunk k). Rows of class c are
    // h = c + 3m, m in [0,85); this block's group g takes m = 5k + g.
    const int c = blockIdx.x / CHUNKS;
    const int k = blockIdx.x - c * CHUNKS;
    const int h = c + 3 * (G * k + g);
    const bool rowvalid = (h < HO);

    if (rowvalid && t < TGRP) {
        const int oh = h + PAD;          // padded row coord 3..255

        // Valid kernel-row plane offsets (uniform per group). ni is 2 or 3.
        int offi[3];
        int ni = 0;
        const int ri = oh % 3;
        #pragma unroll
        for (int s = 0; s < 3; ++s) {
            const int i = ri + 3 * s;
            if (i < K) {
                const int d = oh - i;
                if (d >= 0) {
                    const int ph = d / 3;
                    if (ph < NH) offi[ni++] = i * (K * PLANE) + ph * NW;
                }
            }
        }

        const float* __restrict__ base =
            xp + (size_t)bc * (K * K * PLANE) + t;

        const bool p012 = (t <= NW - 2);   // t <= 83
        const bool p6   = (t >= 1);

        float a0 = 0.f, a1 = 0.f, a2 = 0.f;

        if (ni == 3) {                     // uniform within the group
            accum_plane(base + offi[0], p012, p6, a0, a1, a2);
            accum_plane(base + offi[1], p012, p6, a0, a1, a2);
            accum_plane(base + offi[2], p012, p6, a0, a1, a2);
            const float inv0  = (p012 && p6) ? (1.f / 9.f) : (1.f / 6.f);
            const float inv12 = p012 ? (1.f / 6.f) : (1.f / 3.f);
            a0 *= inv0;  a1 *= inv12;  a2 *= inv12;
        } else {
            accum_plane(base + offi[0], p012, p6, a0, a1, a2);
            accum_plane(base + offi[1], p012, p6, a0, a1, a2);
            const float inv0  = (p012 && p6) ? (1.f / 6.f) : (1.f / 4.f);
            const float inv12 = p012 ? (1.f / 4.f) : (1.f / 2.f);
            a0 *= inv0;  a1 *= inv12;  a2 *= inv12;
        }

        // Stage: stride-3 STS, bank-conflict-free (gcd(3,32)=1).
        sm[g][3 * t + 0] = a0;
        sm[g][3 * t + 1] = a1;
        sm[g][3 * t + 2] = a2;
    }

    __syncthreads();

    // Each group stores its own row: 253 floats, 96 threads, 3 passes.
    if (rowvalid) {
        float* __restrict__ orow = out + ((size_t)bc * HO + h) * WO;
        #pragma unroll
        for (int idx = 0; idx < 3; ++idx) {
            const int w = t + idx * TPG;
            if (w < WO) orow[w] = sm[g][w];
        }
    }
}

extern "C" void kernel_launch(void* const* d_in, const int* in_sizes, int n_in,
                              void* d_out, int out_size)
{
    (void)in_sizes; (void)n_in; (void)out_size;
    const float* xp = (const float*)d_in[0];
    float* out = (float*)d_out;

    dim3 grid(3 * CHUNKS, BC);   // 51 x 256
    dim3 block(TPB);             // 480
    patch2im_kernel<<<grid, block>>>(xp, out);
}

// round 16
// speedup vs baseline: 1.0061x; 1.0061x over previous
#include <cuda_runtime.h>

// Patch2Im / fold (col2im) with averaging and crop.
// Input : x_patch [B=4, C=64, K=7, K=7, NH=85, NW=85] fp32 (row-major)
// Output: [B, C, 253, 253] fp32 (padded frame 259x259, crop 3 each side)
//
// v8 = v2/v6 skeleton (direct immediate-offset gather, best @66us) with a
// cache-policy fix. Each block's 21 read ranges are 340B and UNALIGNED, so
// their boundary 32B sectors are shared with the adjacent-ph ranges read by
// the h+-3 blocks (co-resident in the same wave). Reads therefore use the
// DEFAULT (evict-normal) policy so the shared lines survive in L2 for the
// neighbor block (the previous __ldcs evict-first forced a second DRAM
// fetch). Output stores are write-once -> streamed with __stcs so they do
// not displace those read lines.
//
// Thread t owns output columns ow = 3t+3+e (e=0,1,2). For kernel column j,
// the output with e=j%3 reads patch column pw = t+1 - j/3, so all 7 loads
// of a kernel-row plane sit at FIXED immediate offsets from (plane_base+t):
//   {+1, P+1, 2P+1, 3P, 4P, 5P, 6P-1},  P = 85*85.
// Normalization counts are analytic; reciprocals are selected constants.

namespace {
constexpr int K     = 7;
constexpr int NH    = 85;
constexpr int NW    = 85;
constexpr int PLANE = NH * NW;          // 7225
constexpr int PAD   = 3;
constexpr int HO    = 253;
constexpr int WO    = 253;
constexpr int BC    = 4 * 64;
constexpr int TPB   = 96;               // 85 compute lanes + store helpers
constexpr int TGRP  = 85;
}

// One kernel-row plane: 7 loads at constant immediate offsets, boundary
// groups predicated (@P LDG). Default cache policy (evict-normal) so the
// shared boundary sectors stay in L2 for the h+-3 neighbor blocks.
__device__ __forceinline__ void accum_plane(const float* __restrict__ q,
                                            bool p012, bool p6,
                                            float& a0, float& a1, float& a2)
{
    if (p012) {                               // pw = t+1 (t <= 83)
        a0 += q[1];                           // j=0
        a1 += q[PLANE + 1];                   // j=1
        a2 += q[2 * PLANE + 1];               // j=2
    }
    a0 += q[3 * PLANE];                       // j=3 (pw = t)
    a1 += q[4 * PLANE];                       // j=4
    a2 += q[5 * PLANE];                       // j=5
    if (p6)                                   // pw = t-1 (t >= 1)
        a0 += q[6 * PLANE - 1];               // j=6
}

__global__ __launch_bounds__(TPB)
void patch2im_kernel(const float* __restrict__ xp, float* __restrict__ out)
{
    const int h  = blockIdx.x;           // output row 0..252
    const int bc = blockIdx.y;           // fused batch*channel
    const int t  = threadIdx.x;          // 0..95

    __shared__ float sm[TGRP * 3];

    const int oh = h + PAD;              // padded row coord 3..255

    // Valid kernel-row plane offsets for this row (uniform per block).
    int offi[3];
    int ni = 0;
    const int ri = oh % 3;
    #pragma unroll
    for (int s = 0; s < 3; ++s) {
        const int i = ri + 3 * s;
        if (i < K) {
            const int d = oh - i;
            if (d >= 0) {
                const int ph = d / 3;
                if (ph < NH) offi[ni++] = i * (K * PLANE) + ph * NW;
            }
        }
    }
    // ni is always 2 or 3 for oh in [3, 255].

    if (t < TGRP) {
        const float* __restrict__ base =
            xp + (size_t)bc * (K * K * PLANE) + t;

        const bool p012 = (t <= NW - 2);   // t <= 83
        const bool p6   = (t >= 1);

        float a0 = 0.f, a1 = 0.f, a2 = 0.f;

        if (ni == 3) {                     // uniform branch (whole block)
            accum_plane(base + offi[0], p012, p6, a0, a1, a2);
            accum_plane(base + offi[1], p012, p6, a0, a1, a2);
            accum_plane(base + offi[2], p012, p6, a0, a1, a2);
            const float inv0  = (p012 && p6) ? (1.f / 9.f) : (1.f / 6.f);
            const float inv12 = p012 ? (1.f / 6.f) : (1.f / 3.f);
            a0 *= inv0;  a1 *= inv12;  a2 *= inv12;
        } else {
            accum_plane(base + offi[0], p012, p6, a0, a1, a2);
            accum_plane(base + offi[1], p012, p6, a0, a1, a2);
            const float inv0  = (p012 && p6) ? (1.f / 6.f) : (1.f / 4.f);
            const float inv12 = p012 ? (1.f / 4.f) : (1.f / 2.f);
            a0 *= inv0;  a1 *= inv12;  a2 *= inv12;
        }

        // Stage: stride-3 STS, bank-conflict-free (gcd(3,32)=1).
        sm[3 * t + 0] = a0;
        sm[3 * t + 1] = a1;
        sm[3 * t + 2] = a2;
    }

    __syncthreads();

    // Coalesced row store: 253 floats with 96 threads, 3 passes.
    // Streamed (__stcs): output is never re-read, keep L2 for read reuse.
    float* __restrict__ orow = out + ((size_t)bc * HO + h) * WO;
    #pragma unroll
    for (int idx = 0; idx < 3; ++idx) {
        const int w = t + idx * TPB;
        if (w < WO) __stcs(orow + w, sm[w]);
    }
}

extern "C" void kernel_launch(void* const* d_in, const int* in_sizes, int n_in,
                              void* d_out, int out_size)
{
    (void)in_sizes; (void)n_in; (void)out_size;
    const float* xp = (const float*)d_in[0];
    float* out = (float*)d_out;

    dim3 grid(HO, BC);   // 253 x 256
    dim3 block(TPB);
    patch2im_kernel<<<grid, block>>>(xp, out);
}

// round 17
// speedup vs baseline: 1.0100x; 1.0038x over previous
#include <cuda_runtime.h>

// Patch2Im / fold (col2im) with averaging and crop.
// Input : x_patch [B=4, C=64, K=7, K=7, NH=85, NW=85] fp32 (row-major)
// Output: [B, C, 253, 253] fp32 (padded frame 259x259, crop 3 each side)
//
// FINAL (v6): direct immediate-offset gather + deep load batching.
// Thread t owns output columns ow = 3t+3+e (e=0,1,2). For kernel column j,
// the output with e=j%3 reads patch column pw = t+1 - j/3, so all 7 loads
// of a kernel-row plane sit at FIXED immediate offsets from (plane_base+t):
//   {+1, P+1, 2P+1, 3P, 4P, 5P, 6P-1},  P = 85*85.
// All 21 loads are issued into a flat local array BEFORE any accumulation
// (single scoreboard drain, maximal loads-in-flight per warp). __ldcs on
// reads (read-once: evict-first keeps L2 clean so h+-3 boundary-sector
// sharing hits), default-policy stores (1012B rows straddle lines shared
// with adjacent-h blocks; evict-normal lets L2 merge them).
// Measured: 59.5us kernel @ 6.25TB/s = LTS chip cap; <2% traffic waste.

namespace {
constexpr int K     = 7;
constexpr int NH    = 85;
constexpr int NW    = 85;
constexpr int PLANE = NH * NW;          // 7225
constexpr int PAD   = 3;
constexpr int HO    = 253;
constexpr int WO    = 253;
constexpr int BC    = 4 * 64;
constexpr int TPB   = 96;
constexpr int TGRP  = 85;
}

// Issue the 7 loads of one kernel-row plane into v[0..6] (predicated).
__device__ __forceinline__ void load_plane(const float* __restrict__ q,
                                           bool p012, bool p6, float* v)
{
    v[0] = p012 ? __ldcs(q + 1)             : 0.f;   // j=0, pw=t+1
    v[1] = p012 ? __ldcs(q + PLANE + 1)     : 0.f;   // j=1
    v[2] = p012 ? __ldcs(q + 2 * PLANE + 1) : 0.f;   // j=2
    v[3] = __ldcs(q + 3 * PLANE);                    // j=3, pw=t
    v[4] = __ldcs(q + 4 * PLANE);                    // j=4
    v[5] = __ldcs(q + 5 * PLANE);                    // j=5
    v[6] = p6 ? __ldcs(q + 6 * PLANE - 1)   : 0.f;   // j=6, pw=t-1
}

__global__ __launch_bounds__(TPB, 10)
void patch2im_kernel(const float* __restrict__ xp, float* __restrict__ out)
{
    const int h  = blockIdx.x;           // output row 0..252
    const int bc = blockIdx.y;           // fused batch*channel
    const int t  = threadIdx.x;          // 0..95

    __shared__ float sm[TGRP * 3];

    const int oh = h + PAD;              // padded row coord 3..255

    // Valid kernel-row plane offsets for this row (uniform per block).
    int offi[3];
    int ni = 0;
    const int ri = oh % 3;
    #pragma unroll
    for (int s = 0; s < 3; ++s) {
        const int i = ri + 3 * s;
        if (i < K) {
            const int d = oh - i;
            if (d >= 0) {
                const int ph = d / 3;
                if (ph < NH) offi[ni++] = i * (K * PLANE) + ph * NW;
            }
        }
    }
    // ni is always 2 or 3 for oh in [3, 255].

    if (t < TGRP) {
        const float* __restrict__ base =
            xp + (size_t)bc * (K * K * PLANE) + t;

        const bool p012 = (t <= NW - 2);   // t <= 83
        const bool p6   = (t >= 1);

        float a0, a1, a2;

        if (ni == 3) {                     // uniform branch (whole block)
            float v[21];
            load_plane(base + offi[0], p012, p6, v);
            load_plane(base + offi[1], p012, p6, v + 7);
            load_plane(base + offi[2], p012, p6, v + 14);

            a0 = (v[0] + v[3]) + (v[6] + v[7]) + (v[10] + v[13])
               + (v[14] + v[17]) + v[20];
            a1 = (v[1] + v[4]) + (v[8] + v[11]) + (v[15] + v[18]);
            a2 = (v[2] + v[5]) + (v[9] + v[12]) + (v[16] + v[19]);

            const float inv0  = (p012 && p6) ? (1.f / 9.f) : (1.f / 6.f);
            const float inv12 = p012 ? (1.f / 6.f) : (1.f / 3.f);
            a0 *= inv0;  a1 *= inv12;  a2 *= inv12;
        } else {
            float v[14];
            load_plane(base + offi[0], p012, p6, v);
            load_plane(base + offi[1], p012, p6, v + 7);

            a0 = (v[0] + v[3]) + (v[6] + v[7]) + (v[10] + v[13]);
            a1 = (v[1] + v[4]) + (v[8] + v[11]);
            a2 = (v[2] + v[5]) + (v[9] + v[12]);

            const float inv0  = (p012 && p6) ? (1.f / 6.f) : (1.f / 4.f);
            const float inv12 = p012 ? (1.f / 4.f) : (1.f / 2.f);
            a0 *= inv0;  a1 *= inv12;  a2 *= inv12;
        }

        // Stage: stride-3 STS, bank-conflict-free (gcd(3,32)=1).
        sm[3 * t + 0] = a0;
        sm[3 * t + 1] = a1;
        sm[3 * t + 2] = a2;
    }

    __syncthreads();

    // Coalesced row store: 253 floats with 96 threads, 3 passes.
    float* __restrict__ orow = out + ((size_t)bc * HO + h) * WO;
    #pragma unroll
    for (int idx = 0; idx < 3; ++idx) {
        const int w = t + idx * TPB;
        if (w < WO) orow[w] = sm[w];
    }
}

extern "C" void kernel_launch(void* const* d_in, const int* in_sizes, int n_in,
                              void* d_out, int out_size)
{
    (void)in_sizes; (void)n_in; (void)out_size;
    const float* xp = (const float*)d_in[0];
    float* out = (float*)d_out;

    dim3 grid(HO, BC);   // 253 x 256
    dim3 block(TPB);
    patch2im_kernel<<<grid, block>>>(xp, out);
}